// round 13
// baseline (speedup 1.0000x reference)
#include <cuda_runtime.h>

// AnnularDilatedKNN: B=4, N=4096, C=64, SAMPLE=16, DILATED_RATE=2 -> NSAMPLE=32, K_out=16
// radius^2 = 256.
//
// R13 = R12 with the fused-gather thread-budget bug fixed: the xyz branch needs
// 256 blocks (65536 threads, one per (b,n,k4)); R11/R12 gave it only 64 ->
// 3/4 of the dilated_xyz output stayed poisoned (the identical rel_err=0.864).
// Gather split is now [0,256) xyz / [256,1280) feature, bodies verbatim R10.
// Everything else identical to R12: 3-D 20^3 grid (width 17), warp-per-sorted-
// query with 9 contiguous runs, bitmap + verified popc-prefix selection.
// Predicate/sq/selection byte-identical to rel_err=0.0 code.

#define NB     4
#define NP     4096
#define KOUT   16
#define NC     20
#define NCELL3 (NC * NC * NC)       // 8000
#define CMIN   (-170.0f)
#define INVC   (1.0f / 17.0f)
#define QW     16                   // warps (queries) per query block
#define CBLK   64                   // count/scatter blocks (256 thr), 16 per batch

__device__ float4 g_cand[NB * NP];           // cell-sorted (x,y,z,sq)
__device__ int    g_sid[NB * NP];            // original index per sorted slot
__device__ int    g_pcell[NB * NP];          // cell per original point
__device__ int    g_blkcnt[CBLK * NCELL3];
__device__ int    g_blkbase[CBLK * NCELL3];
__device__ int    g_cstart[NB * (NCELL3 + 1)];
__device__ int    g_ids[NB * NP * KOUT];

__device__ __forceinline__ float sq3(float x, float y, float z) {
    // jnp.sum(xyz*xyz, -1): left-to-right, separately rounded products (no fma).
    return __fadd_rn(__fadd_rn(__fmul_rn(x, x), __fmul_rn(y, y)), __fmul_rn(z, z));
}

__device__ __forceinline__ int cell1(float v) {
    int c = (int)floorf(__fmul_rn(__fadd_rn(v, -CMIN), INVC));
    return min(max(c, 0), NC - 1);
}

// ---- build 1: per-block cell counts (smem, no global atomics) ----
__global__ __launch_bounds__(256) void count_kernel(const float* __restrict__ xyz) {
    __shared__ int sc[NCELL3];                 // 32000 B
    const int i = blockIdx.x * 256 + threadIdx.x;
    for (int k = threadIdx.x; k < NCELL3; k += 256) sc[k] = 0;
    __syncthreads();
    const float x = xyz[3 * i + 0];
    const float y = xyz[3 * i + 1];
    const float z = xyz[3 * i + 2];
    const int c = (cell1(z) * NC + cell1(y)) * NC + cell1(x);
    g_pcell[i] = c;
    atomicAdd(&sc[c], 1);
    __syncthreads();
    for (int k = threadIdx.x; k < NCELL3; k += 256)
        g_blkcnt[blockIdx.x * NCELL3 + k] = sc[k];
}

// ---- build 2: per-batch exclusive scan over 8000 cells + per-block bases ----
__global__ __launch_bounds__(1024) void scan_kernel() {
    __shared__ int wsum[32];
    const int b = blockIdx.x;
    const int tid = threadIdx.x, lane = tid & 31, wid = tid >> 5;

    int s = 0;
    #pragma unroll
    for (int j = 0; j < 8; ++j) {
        const int c = tid * 8 + j;
        if (c < NCELL3)
            for (int k = 0; k < 16; ++k)
                s += g_blkcnt[(b * 16 + k) * NCELL3 + c];
    }
    int incl = s;
    #pragma unroll
    for (int off = 1; off < 32; off <<= 1) {
        const int t = __shfl_up_sync(0xffffffffu, incl, off);
        if (lane >= off) incl += t;
    }
    if (lane == 31) wsum[wid] = incl;
    __syncthreads();
    if (wid == 0) {
        int wv = wsum[lane];
        int wi = wv;
        #pragma unroll
        for (int off = 1; off < 32; off <<= 1) {
            const int t = __shfl_up_sync(0xffffffffu, wi, off);
            if (lane >= off) wi += t;
        }
        wsum[lane] = wi - wv;
    }
    __syncthreads();
    int run = (incl - s) + wsum[wid];
    #pragma unroll
    for (int j = 0; j < 8; ++j) {
        const int c = tid * 8 + j;
        if (c < NCELL3) {
            g_cstart[b * (NCELL3 + 1) + c] = run;
            for (int k = 0; k < 16; ++k) {
                const int v = g_blkcnt[(b * 16 + k) * NCELL3 + c];
                g_blkbase[(b * 16 + k) * NCELL3 + c] = run;
                run += v;
            }
            if (c == NCELL3 - 1) g_cstart[b * (NCELL3 + 1) + NCELL3] = run;  // == NP
        }
    }
}

// ---- build 3: scatter (cursors in smem: 32KB; bases read from global) ----
__global__ __launch_bounds__(256) void scatter_kernel(const float* __restrict__ xyz) {
    __shared__ int sc[NCELL3];                 // cursors only (32000 B)
    const int i = blockIdx.x * 256 + threadIdx.x;
    const int b = i >> 12;
    for (int k = threadIdx.x; k < NCELL3; k += 256) sc[k] = 0;
    __syncthreads();
    const int c = g_pcell[i];
    const int lr = atomicAdd(&sc[c], 1);
    const int base = g_blkbase[blockIdx.x * NCELL3 + c];
    const float x = xyz[3 * i + 0];
    const float y = xyz[3 * i + 1];
    const float z = xyz[3 * i + 2];
    const int gi = (b << 12) + base + lr;
    g_cand[gi] = make_float4(x, y, z, sq3(x, y, z));
    g_sid[gi] = i & (NP - 1);
}

// ---- query: warp per SORTED query; 9 contiguous 3-D neighborhood runs ----
__global__ __launch_bounds__(32 * QW) void query_kernel() {
    __shared__ unsigned bm[QW][128];
    __shared__ int cum[QW][128];

    const int warp = threadIdx.x >> 5, lane = threadIdx.x & 31;
    const int p = blockIdx.x * QW + warp;      // sorted position, 0..16383
    const int b = p >> 12;
    const int bb = b << 12;

    const float4 qc = g_cand[p];
    const int qn = g_sid[p];
    const float xn = qc.x, yn = qc.y, zn = qc.z, sqn = qc.w;

    const int cx = cell1(xn), cy = cell1(yn), cz = cell1(zn);
    const int xlo = max(cx - 1, 0), xhi = min(cx + 1, NC - 1);
    const int ylo = max(cy - 1, 0), yhi = min(cy + 1, NC - 1);
    const int zlo = max(cz - 1, 0), zhi = min(cz + 1, NC - 1);
    const int* __restrict__ cs = g_cstart + b * (NCELL3 + 1);

    #pragma unroll
    for (int k = 0; k < 4; ++k) bm[warp][lane * 4 + k] = 0u;
    __syncwarp();

    const float4* __restrict__ cand = g_cand + bb;
    const int* __restrict__ sid = g_sid + bb;

    for (int zz = zlo; zz <= zhi; ++zz) {
        for (int yy = ylo; yy <= yhi; ++yy) {
            const int row = (zz * NC + yy) * NC;
            const int st = cs[row + xlo];
            const int e  = cs[row + xhi + 1];
            #pragma unroll 4
            for (int i = st + lane; i < e; i += 32) {
                const float4 c = cand[i];
                // byte-identical verified predicate
                const float dot = fmaf(zn, c.z, fmaf(yn, c.y, __fmul_rn(xn, c.x)));
                const float d2  = __fsub_rn(__fadd_rn(sqn, c.w), __fmul_rn(2.0f, dot));
                if (d2 < 256.0f) {
                    const int id = sid[i];
                    atomicOr(&bm[warp][id >> 5], 1u << (id & 31));
                }
            }
        }
    }
    __syncwarp();

    // verified selection: popc prefix over 128 words, ranks {0,16..30}
    int c4[4];
    int lsum = 0;
    #pragma unroll
    for (int k = 0; k < 4; ++k) {
        c4[k] = __popc(bm[warp][lane * 4 + k]);
        lsum += c4[k];
    }
    int incl = lsum;
    #pragma unroll
    for (int off = 1; off < 32; off <<= 1) {
        const int t = __shfl_up_sync(0xffffffffu, incl, off);
        if (lane >= off) incl += t;
    }
    const int cnt = __shfl_sync(0xffffffffu, incl, 31);
    int base = incl - lsum;
    #pragma unroll
    for (int k = 0; k < 4; ++k) {
        cum[warp][lane * 4 + k] = base;
        base += c4[k];
    }
    __syncwarp();

    int own = 0;
    const int t = (lane == 0) ? 0 : lane + 15;
    if (lane < 16 && t < cnt) {
        int lo = 0, hi = 127;
        while (lo < hi) {                        // largest word with cum <= t
            const int mid = (lo + hi + 1) >> 1;
            if (cum[warp][mid] <= t) lo = mid; else hi = mid - 1;
        }
        unsigned w = bm[warp][lo];
        int r = t - cum[warp][lo];
        while (r--) w &= (w - 1u);
        own = (lo << 5) + (__ffs(w) - 1);
    }
    const int h0 = __shfl_sync(0xffffffffu, own, 0);  // center (cnt>=1: self-hit)
    if (lane < 16) g_ids[((bb + qn) << 4) + lane] = (t < cnt) ? own : h0;
}

// ---- fused gather: blocks [0,256) = xyz planes, [256,1280) = feature planes ----
__global__ __launch_bounds__(256) void gather_kernel(const float* __restrict__ xyz,
                                                     const float* __restrict__ feat,
                                                     float* __restrict__ out) {
    if (blockIdx.x < 256) {
        const int t  = blockIdx.x * 256 + threadIdx.x;    // b(2)|n(12)|k4(2), 65536 total
        const int k4 = t & 3;
        const int n  = (t >> 2) & (NP - 1);
        const int b  = t >> 14;
        const int bb = b << 12;
        const int4 id4 = reinterpret_cast<const int4*>(g_ids)[t];
        const int o4 = (n << 2) + k4;

        const float* xb = xyz + 3 * bb;
        const float x0 = xb[3 * id4.x], y0 = xb[3 * id4.x + 1], z0 = xb[3 * id4.x + 2];
        const float x1 = xb[3 * id4.y], y1 = xb[3 * id4.y + 1], z1 = xb[3 * id4.y + 2];
        const float x2 = xb[3 * id4.z], y2 = xb[3 * id4.z + 1], z2 = xb[3 * id4.z + 2];
        const float x3 = xb[3 * id4.w], y3 = xb[3 * id4.w + 1], z3 = xb[3 * id4.w + 2];
        float4* o = reinterpret_cast<float4*>(out);
        o[((b * 3 + 0) << 14) + o4] = make_float4(x0, x1, x2, x3);
        o[((b * 3 + 1) << 14) + o4] = make_float4(y0, y1, y2, y3);
        o[((b * 3 + 2) << 14) + o4] = make_float4(z0, z1, z2, z3);
    } else {
        const int t  = (blockIdx.x - 256) * 256 + threadIdx.x;  // b(2)|n(12)|k4(2)|cq(2)
        const int cq = t & 3;
        const int k4 = (t >> 2) & 3;
        const int n  = (t >> 4) & (NP - 1);
        const int b  = t >> 16;
        const int bb = b << 12;
        const int4 id4 = reinterpret_cast<const int4*>(g_ids)[((bb + n) << 2) + k4];
        const int o4 = (n << 2) + k4;

        const float4* f0 = reinterpret_cast<const float4*>(feat) + ((bb + id4.x) << 4) + (cq << 2);
        const float4* f1 = reinterpret_cast<const float4*>(feat) + ((bb + id4.y) << 4) + (cq << 2);
        const float4* f2 = reinterpret_cast<const float4*>(feat) + ((bb + id4.z) << 4) + (cq << 2);
        const float4* f3 = reinterpret_cast<const float4*>(feat) + ((bb + id4.w) << 4) + (cq << 2);

        float4* of = reinterpret_cast<float4*>(out) + ((12 + b * 64 + (cq << 4)) << 14) + o4;
        #pragma unroll
        for (int j = 0; j < 4; ++j) {
            const float4 v0 = f0[j], v1 = f1[j], v2 = f2[j], v3 = f3[j];
            of[(4 * j + 0) << 14] = make_float4(v0.x, v1.x, v2.x, v3.x);
            of[(4 * j + 1) << 14] = make_float4(v0.y, v1.y, v2.y, v3.y);
            of[(4 * j + 2) << 14] = make_float4(v0.z, v1.z, v2.z, v3.z);
            of[(4 * j + 3) << 14] = make_float4(v0.w, v1.w, v2.w, v3.w);
        }
    }
}

extern "C" void kernel_launch(void* const* d_in, const int* in_sizes, int n_in,
                              void* d_out, int out_size) {
    const float* xyz  = (const float*)d_in[0];
    const float* feat = (const float*)d_in[1];
    float* out = (float*)d_out;

    count_kernel<<<CBLK, 256>>>(xyz);
    scan_kernel<<<NB, 1024>>>();
    scatter_kernel<<<CBLK, 256>>>(xyz);
    query_kernel<<<(NB * NP) / QW, 32 * QW>>>();
    gather_kernel<<<256 + (NB * NP * KOUT) / 256, 256>>>(xyz, feat, out);
}

// round 14
// speedup vs baseline: 2.9728x; 2.9728x over previous
#include <cuda_runtime.h>

// AnnularDilatedKNN: B=4, N=4096, C=64, SAMPLE=16, DILATED_RATE=2 -> NSAMPLE=32, K_out=16
// radius^2 = 256.
//
// R14 = R10 winner (2-D 20x20 grid, warp-per-sorted-query, bitmap + verified
// popc-prefix selection) + fused gather (correct 256/1024 split, verified in
// R13) + query eval loop unrolled x2 per lane (stride 64, guarded 2nd load;
// predicate per candidate byte-identical, bitmap order-independent).
// 3-D grid reverted: R13 measured it as net loss (query 29.2 vs 27.2, build +100us).

#define NB     4
#define NP     4096
#define KOUT   16
#define NCY    20
#define NCZ    20
#define NCELL2 (NCY * NCZ)          // 400
#define CMIN   (-170.0f)
#define INVC   (1.0f / 17.0f)
#define QW     16                   // warps (queries) per query block
#define CBLK   64                   // count/scatter blocks (256 thr), 16 per batch

__device__ float4 g_cand[NB * NP];           // cell-sorted (x,y,z,sq)
__device__ int    g_sid[NB * NP];            // original index per sorted slot
__device__ int    g_pcell[NB * NP];          // cell per original point
__device__ int    g_blkcnt[CBLK * NCELL2];
__device__ int    g_blkbase[CBLK * NCELL2];
__device__ int    g_cstart[NB * (NCELL2 + 1)];
__device__ int    g_ids[NB * NP * KOUT];

__device__ __forceinline__ float sq3(float x, float y, float z) {
    // jnp.sum(xyz*xyz, -1): left-to-right, separately rounded products (no fma).
    return __fadd_rn(__fadd_rn(__fmul_rn(x, x), __fmul_rn(y, y)), __fmul_rn(z, z));
}

__device__ __forceinline__ int cell1(float v) {
    int c = (int)floorf(__fmul_rn(__fadd_rn(v, -CMIN), INVC));
    return min(max(c, 0), NCY - 1);
}

// ---- build 1: per-block cell counts ----
__global__ __launch_bounds__(256) void count_kernel(const float* __restrict__ xyz) {
    __shared__ int sc[NCELL2];
    const int i = blockIdx.x * 256 + threadIdx.x;
    for (int k = threadIdx.x; k < NCELL2; k += 256) sc[k] = 0;
    __syncthreads();
    const float y = xyz[3 * i + 1];
    const float z = xyz[3 * i + 2];
    const int c = cell1(z) * NCY + cell1(y);
    g_pcell[i] = c;
    atomicAdd(&sc[c], 1);
    __syncthreads();
    for (int k = threadIdx.x; k < NCELL2; k += 256)
        g_blkcnt[blockIdx.x * NCELL2 + k] = sc[k];
}

// ---- build 2: per-batch exclusive scan over 400 cells + per-block bases ----
__global__ __launch_bounds__(512) void scan_kernel() {
    __shared__ int wsum[16];
    const int b = blockIdx.x;
    const int tid = threadIdx.x, lane = tid & 31, wid = tid >> 5;

    int cnts[16];
    int tot = 0;
    if (tid < NCELL2) {
        #pragma unroll
        for (int k = 0; k < 16; ++k) {
            cnts[k] = g_blkcnt[(b * 16 + k) * NCELL2 + tid];
            tot += cnts[k];
        }
    }
    int incl = (tid < NCELL2) ? tot : 0;
    #pragma unroll
    for (int off = 1; off < 32; off <<= 1) {
        const int t = __shfl_up_sync(0xffffffffu, incl, off);
        if (lane >= off) incl += t;
    }
    if (lane == 31) wsum[wid] = incl;
    __syncthreads();
    if (wid == 0 && lane < 16) {
        int wv = wsum[lane];
        int wi = wv;
        #pragma unroll
        for (int off = 1; off < 16; off <<= 1) {
            const int t = __shfl_up_sync(0x0000ffffu, wi, off);
            if (lane >= off) wi += t;
        }
        wsum[lane] = wi - wv;
    }
    __syncthreads();
    if (tid < NCELL2) {
        const int excl = (incl - tot) + wsum[wid];
        g_cstart[b * (NCELL2 + 1) + tid] = excl;
        if (tid == NCELL2 - 1) g_cstart[b * (NCELL2 + 1) + NCELL2] = excl + tot; // == NP
        int run = excl;
        #pragma unroll
        for (int k = 0; k < 16; ++k) {
            g_blkbase[(b * 16 + k) * NCELL2 + tid] = run;
            run += cnts[k];
        }
    }
}

// ---- build 3: scatter into cell-sorted order (smem atomics only) ----
__global__ __launch_bounds__(256) void scatter_kernel(const float* __restrict__ xyz) {
    __shared__ int sc[NCELL2];
    __shared__ int sb[NCELL2];
    const int i = blockIdx.x * 256 + threadIdx.x;
    const int b = i >> 12;
    for (int k = threadIdx.x; k < NCELL2; k += 256) {
        sc[k] = 0;
        sb[k] = g_blkbase[blockIdx.x * NCELL2 + k];
    }
    __syncthreads();
    const int c = g_pcell[i];
    const int lr = atomicAdd(&sc[c], 1);
    const float x = xyz[3 * i + 0];
    const float y = xyz[3 * i + 1];
    const float z = xyz[3 * i + 2];
    const int gi = (b << 12) + sb[c] + lr;
    g_cand[gi] = make_float4(x, y, z, sq3(x, y, z));
    g_sid[gi] = i & (NP - 1);
}

// ---- query: warp per SORTED query; 3 contiguous 2-D runs; x2 unrolled ----
__global__ __launch_bounds__(32 * QW) void query_kernel() {
    __shared__ unsigned bm[QW][128];
    __shared__ int cum[QW][128];

    const int warp = threadIdx.x >> 5, lane = threadIdx.x & 31;
    const int p = blockIdx.x * QW + warp;        // sorted position, 0..16383
    const int b = p >> 12;
    const int bb = b << 12;

    const float4 qc = g_cand[p];
    const int qn = g_sid[p];
    const float xn = qc.x, yn = qc.y, zn = qc.z, sqn = qc.w;

    const int cy = cell1(yn), cz = cell1(zn);
    const int ylo = max(cy - 1, 0), yhi = min(cy + 1, NCY - 1);
    const int zlo = max(cz - 1, 0), zhi = min(cz + 1, NCZ - 1);
    const int* __restrict__ cs = g_cstart + b * (NCELL2 + 1);
    int seg_s[3], seg_e[3];
    int nseg = 0;
    for (int zz = zlo; zz <= zhi; ++zz) {
        seg_s[nseg] = cs[zz * NCY + ylo];
        seg_e[nseg] = cs[zz * NCY + yhi + 1];
        ++nseg;
    }

    #pragma unroll
    for (int k = 0; k < 4; ++k) bm[warp][lane * 4 + k] = 0u;
    __syncwarp();

    const float4* __restrict__ cand = g_cand + bb;
    const int* __restrict__ sid = g_sid + bb;

    for (int sgi = 0; sgi < nseg; ++sgi) {
        const int e = seg_e[sgi];
        #pragma unroll 2
        for (int i = seg_s[sgi] + lane; i < e; i += 64) {
            // two independent candidates per iteration (2nd guarded)
            const float4 c1 = cand[i];
            const int i2 = i + 32;
            float4 c2;
            const bool has2 = i2 < e;
            if (has2) c2 = cand[i2];

            // byte-identical verified predicate (per candidate)
            const float dot1 = fmaf(zn, c1.z, fmaf(yn, c1.y, __fmul_rn(xn, c1.x)));
            const float d21  = __fsub_rn(__fadd_rn(sqn, c1.w), __fmul_rn(2.0f, dot1));
            if (d21 < 256.0f) {
                const int id = sid[i];
                atomicOr(&bm[warp][id >> 5], 1u << (id & 31));
            }
            if (has2) {
                const float dot2 = fmaf(zn, c2.z, fmaf(yn, c2.y, __fmul_rn(xn, c2.x)));
                const float d22  = __fsub_rn(__fadd_rn(sqn, c2.w), __fmul_rn(2.0f, dot2));
                if (d22 < 256.0f) {
                    const int id = sid[i2];
                    atomicOr(&bm[warp][id >> 5], 1u << (id & 31));
                }
            }
        }
    }
    __syncwarp();

    // verified selection: popc prefix over 128 words, ranks {0,16..30}
    int c4[4];
    int lsum = 0;
    #pragma unroll
    for (int k = 0; k < 4; ++k) {
        c4[k] = __popc(bm[warp][lane * 4 + k]);
        lsum += c4[k];
    }
    int incl = lsum;
    #pragma unroll
    for (int off = 1; off < 32; off <<= 1) {
        const int t = __shfl_up_sync(0xffffffffu, incl, off);
        if (lane >= off) incl += t;
    }
    const int cnt = __shfl_sync(0xffffffffu, incl, 31);
    int base = incl - lsum;
    #pragma unroll
    for (int k = 0; k < 4; ++k) {
        cum[warp][lane * 4 + k] = base;
        base += c4[k];
    }
    __syncwarp();

    int own = 0;
    const int t = (lane == 0) ? 0 : lane + 15;
    if (lane < 16 && t < cnt) {
        int lo = 0, hi = 127;
        while (lo < hi) {                        // largest word with cum <= t
            const int mid = (lo + hi + 1) >> 1;
            if (cum[warp][mid] <= t) lo = mid; else hi = mid - 1;
        }
        unsigned w = bm[warp][lo];
        int r = t - cum[warp][lo];
        while (r--) w &= (w - 1u);
        own = (lo << 5) + (__ffs(w) - 1);
    }
    const int h0 = __shfl_sync(0xffffffffu, own, 0);  // center (cnt>=1: self-hit)
    if (lane < 16) g_ids[((bb + qn) << 4) + lane] = (t < cnt) ? own : h0;
}

// ---- fused gather: blocks [0,256) = xyz planes, [256,1280) = feature planes ----
__global__ __launch_bounds__(256) void gather_kernel(const float* __restrict__ xyz,
                                                     const float* __restrict__ feat,
                                                     float* __restrict__ out) {
    if (blockIdx.x < 256) {
        const int t  = blockIdx.x * 256 + threadIdx.x;    // b(2)|n(12)|k4(2), 65536 total
        const int k4 = t & 3;
        const int n  = (t >> 2) & (NP - 1);
        const int b  = t >> 14;
        const int bb = b << 12;
        const int4 id4 = reinterpret_cast<const int4*>(g_ids)[t];
        const int o4 = (n << 2) + k4;

        const float* xb = xyz + 3 * bb;
        const float x0 = xb[3 * id4.x], y0 = xb[3 * id4.x + 1], z0 = xb[3 * id4.x + 2];
        const float x1 = xb[3 * id4.y], y1 = xb[3 * id4.y + 1], z1 = xb[3 * id4.y + 2];
        const float x2 = xb[3 * id4.z], y2 = xb[3 * id4.z + 1], z2 = xb[3 * id4.z + 2];
        const float x3 = xb[3 * id4.w], y3 = xb[3 * id4.w + 1], z3 = xb[3 * id4.w + 2];
        float4* o = reinterpret_cast<float4*>(out);
        o[((b * 3 + 0) << 14) + o4] = make_float4(x0, x1, x2, x3);
        o[((b * 3 + 1) << 14) + o4] = make_float4(y0, y1, y2, y3);
        o[((b * 3 + 2) << 14) + o4] = make_float4(z0, z1, z2, z3);
    } else {
        const int t  = (blockIdx.x - 256) * 256 + threadIdx.x;  // b(2)|n(12)|k4(2)|cq(2)
        const int cq = t & 3;
        const int k4 = (t >> 2) & 3;
        const int n  = (t >> 4) & (NP - 1);
        const int b  = t >> 16;
        const int bb = b << 12;
        const int4 id4 = reinterpret_cast<const int4*>(g_ids)[((bb + n) << 2) + k4];
        const int o4 = (n << 2) + k4;

        const float4* f0 = reinterpret_cast<const float4*>(feat) + ((bb + id4.x) << 4) + (cq << 2);
        const float4* f1 = reinterpret_cast<const float4*>(feat) + ((bb + id4.y) << 4) + (cq << 2);
        const float4* f2 = reinterpret_cast<const float4*>(feat) + ((bb + id4.z) << 4) + (cq << 2);
        const float4* f3 = reinterpret_cast<const float4*>(feat) + ((bb + id4.w) << 4) + (cq << 2);

        float4* of = reinterpret_cast<float4*>(out) + ((12 + b * 64 + (cq << 4)) << 14) + o4;
        #pragma unroll
        for (int j = 0; j < 4; ++j) {
            const float4 v0 = f0[j], v1 = f1[j], v2 = f2[j], v3 = f3[j];
            of[(4 * j + 0) << 14] = make_float4(v0.x, v1.x, v2.x, v3.x);
            of[(4 * j + 1) << 14] = make_float4(v0.y, v1.y, v2.y, v3.y);
            of[(4 * j + 2) << 14] = make_float4(v0.z, v1.z, v2.z, v3.z);
            of[(4 * j + 3) << 14] = make_float4(v0.w, v1.w, v2.w, v3.w);
        }
    }
}

extern "C" void kernel_launch(void* const* d_in, const int* in_sizes, int n_in,
                              void* d_out, int out_size) {
    const float* xyz  = (const float*)d_in[0];
    const float* feat = (const float*)d_in[1];
    float* out = (float*)d_out;

    count_kernel<<<CBLK, 256>>>(xyz);
    scan_kernel<<<NB, 512>>>();
    scatter_kernel<<<CBLK, 256>>>(xyz);
    query_kernel<<<(NB * NP) / QW, 32 * QW>>>();
    gather_kernel<<<256 + (NB * NP * KOUT) / 256, 256>>>(xyz, feat, out);
}

// round 15
// speedup vs baseline: 3.1216x; 1.0501x over previous
#include <cuda_runtime.h>

// AnnularDilatedKNN: B=4, N=4096, C=64, SAMPLE=16, DILATED_RATE=2 -> NSAMPLE=32, K_out=16
// radius^2 = 256.
//
// R15 = R14 with:
//  - finer 2-D grid: 40x40 cells, width 8.5, neighborhood +-2 (5 contiguous
//    z-row segments). evals ~830 -> ~590. Margin: hit => f-span 1.88 < 2.
//  - build condensed to 2 kernels: fused count+scan per batch (emits cstart +
//    cursor) and scatter via global atomic cursors. Within-cell order becomes
//    non-deterministic; output is order-invariant (queries identified via
//    g_sid, hits recorded as bitmap over ORIGINAL ids).
//  - query loop back to plain stride-32 (R14 unroll measured neutral).
// Predicate/sq/selection/gather byte-identical to rel_err=0.0 verified code.

#define NB     4
#define NP     4096
#define KOUT   16
#define NCY    40
#define NCZ    40
#define NCELL2 (NCY * NCZ)          // 1600
#define CMIN   (-170.0f)
#define INVC   (1.0f / 8.5f)
#define QW     16                   // warps (queries) per query block
#define SBLK   64                   // scatter blocks (256 thr), 16 per batch

__device__ float4 g_cand[NB * NP];           // cell-sorted (x,y,z,sq)
__device__ int    g_sid[NB * NP];            // original index per sorted slot
__device__ int    g_pcell[NB * NP];          // cell per original point
__device__ int    g_cstart[NB * (NCELL2 + 1)];
__device__ int    g_cursor[NB * NCELL2];
__device__ int    g_ids[NB * NP * KOUT];

__device__ __forceinline__ float sq3(float x, float y, float z) {
    // jnp.sum(xyz*xyz, -1): left-to-right, separately rounded products (no fma).
    return __fadd_rn(__fadd_rn(__fmul_rn(x, x), __fmul_rn(y, y)), __fmul_rn(z, z));
}

__device__ __forceinline__ int cell1(float v) {
    int c = (int)floorf(__fmul_rn(__fadd_rn(v, -CMIN), INVC));
    return min(max(c, 0), NCY - 1);
}

// ---- build 1: fused count + scan, one block per batch ----
__global__ __launch_bounds__(1024) void build_cs_kernel(const float* __restrict__ xyz) {
    __shared__ int cnt[NCELL2];                // 6400 B
    __shared__ int wsum[32];
    const int b = blockIdx.x, tid = threadIdx.x;
    const int lane = tid & 31, wid = tid >> 5;

    for (int k = tid; k < NCELL2; k += 1024) cnt[k] = 0;
    __syncthreads();

    #pragma unroll
    for (int j = 0; j < 4; ++j) {
        const int i = (b << 12) + tid + j * 1024;
        const float y = xyz[3 * i + 1];
        const float z = xyz[3 * i + 2];
        const int c = cell1(z) * NCY + cell1(y);
        g_pcell[i] = c;
        atomicAdd(&cnt[c], 1);
    }
    __syncthreads();

    // exclusive scan over 1600 cells: 2 cells/thread (threads 0..799)
    const int c0 = tid * 2;
    int v0 = 0, v1 = 0;
    if (c0 < NCELL2) { v0 = cnt[c0]; v1 = cnt[c0 + 1]; }
    const int s = v0 + v1;
    int incl = s;
    #pragma unroll
    for (int off = 1; off < 32; off <<= 1) {
        const int t = __shfl_up_sync(0xffffffffu, incl, off);
        if (lane >= off) incl += t;
    }
    if (lane == 31) wsum[wid] = incl;
    __syncthreads();
    if (wid == 0) {
        int wv = wsum[lane];
        int wi = wv;
        #pragma unroll
        for (int off = 1; off < 32; off <<= 1) {
            const int t = __shfl_up_sync(0xffffffffu, wi, off);
            if (lane >= off) wi += t;
        }
        wsum[lane] = wi - wv;
    }
    __syncthreads();
    if (c0 < NCELL2) {
        const int excl = (incl - s) + wsum[wid];
        g_cstart[b * (NCELL2 + 1) + c0]     = excl;
        g_cstart[b * (NCELL2 + 1) + c0 + 1] = excl + v0;
        g_cursor[b * NCELL2 + c0]     = excl;
        g_cursor[b * NCELL2 + c0 + 1] = excl + v0;
        if (c0 + 1 == NCELL2 - 1)
            g_cstart[b * (NCELL2 + 1) + NCELL2] = excl + v0 + v1;   // == NP
    }
}

// ---- build 2: scatter via global atomic cursors ----
__global__ __launch_bounds__(256) void scatter_kernel(const float* __restrict__ xyz) {
    const int i = blockIdx.x * 256 + threadIdx.x;
    const int b = i >> 12;
    const int c = g_pcell[i];
    const int pos = atomicAdd(&g_cursor[b * NCELL2 + c], 1);
    const float x = xyz[3 * i + 0];
    const float y = xyz[3 * i + 1];
    const float z = xyz[3 * i + 2];
    const int gi = (b << 12) + pos;
    g_cand[gi] = make_float4(x, y, z, sq3(x, y, z));
    g_sid[gi] = i & (NP - 1);
}

// ---- query: warp per SORTED query; 5 contiguous 2-D runs (+-2 cells) ----
__global__ __launch_bounds__(32 * QW) void query_kernel() {
    __shared__ unsigned bm[QW][128];
    __shared__ int cum[QW][128];

    const int warp = threadIdx.x >> 5, lane = threadIdx.x & 31;
    const int p = blockIdx.x * QW + warp;        // sorted position, 0..16383
    const int b = p >> 12;
    const int bb = b << 12;

    const float4 qc = g_cand[p];
    const int qn = g_sid[p];
    const float xn = qc.x, yn = qc.y, zn = qc.z, sqn = qc.w;

    const int cy = cell1(yn), cz = cell1(zn);
    const int ylo = max(cy - 2, 0), yhi = min(cy + 2, NCY - 1);
    const int zlo = max(cz - 2, 0), zhi = min(cz + 2, NCZ - 1);
    const int* __restrict__ cs = g_cstart + b * (NCELL2 + 1);

    #pragma unroll
    for (int k = 0; k < 4; ++k) bm[warp][lane * 4 + k] = 0u;
    __syncwarp();

    const float4* __restrict__ cand = g_cand + bb;
    const int* __restrict__ sid = g_sid + bb;

    for (int zz = zlo; zz <= zhi; ++zz) {
        const int st = cs[zz * NCY + ylo];
        const int e  = cs[zz * NCY + yhi + 1];
        #pragma unroll 4
        for (int i = st + lane; i < e; i += 32) {
            const float4 c = cand[i];
            // byte-identical verified predicate
            const float dot = fmaf(zn, c.z, fmaf(yn, c.y, __fmul_rn(xn, c.x)));
            const float d2  = __fsub_rn(__fadd_rn(sqn, c.w), __fmul_rn(2.0f, dot));
            if (d2 < 256.0f) {
                const int id = sid[i];
                atomicOr(&bm[warp][id >> 5], 1u << (id & 31));
            }
        }
    }
    __syncwarp();

    // verified selection: popc prefix over 128 words, ranks {0,16..30}
    int c4[4];
    int lsum = 0;
    #pragma unroll
    for (int k = 0; k < 4; ++k) {
        c4[k] = __popc(bm[warp][lane * 4 + k]);
        lsum += c4[k];
    }
    int incl = lsum;
    #pragma unroll
    for (int off = 1; off < 32; off <<= 1) {
        const int t = __shfl_up_sync(0xffffffffu, incl, off);
        if (lane >= off) incl += t;
    }
    const int cnt = __shfl_sync(0xffffffffu, incl, 31);
    int base = incl - lsum;
    #pragma unroll
    for (int k = 0; k < 4; ++k) {
        cum[warp][lane * 4 + k] = base;
        base += c4[k];
    }
    __syncwarp();

    int own = 0;
    const int t = (lane == 0) ? 0 : lane + 15;
    if (lane < 16 && t < cnt) {
        int lo = 0, hi = 127;
        while (lo < hi) {                        // largest word with cum <= t
            const int mid = (lo + hi + 1) >> 1;
            if (cum[warp][mid] <= t) lo = mid; else hi = mid - 1;
        }
        unsigned w = bm[warp][lo];
        int r = t - cum[warp][lo];
        while (r--) w &= (w - 1u);
        own = (lo << 5) + (__ffs(w) - 1);
    }
    const int h0 = __shfl_sync(0xffffffffu, own, 0);  // center (cnt>=1: self-hit)
    if (lane < 16) g_ids[((bb + qn) << 4) + lane] = (t < cnt) ? own : h0;
}

// ---- fused gather: blocks [0,256) = xyz planes, [256,1280) = feature planes ----
__global__ __launch_bounds__(256) void gather_kernel(const float* __restrict__ xyz,
                                                     const float* __restrict__ feat,
                                                     float* __restrict__ out) {
    if (blockIdx.x < 256) {
        const int t  = blockIdx.x * 256 + threadIdx.x;    // b(2)|n(12)|k4(2), 65536 total
        const int k4 = t & 3;
        const int n  = (t >> 2) & (NP - 1);
        const int b  = t >> 14;
        const int bb = b << 12;
        const int4 id4 = reinterpret_cast<const int4*>(g_ids)[t];
        const int o4 = (n << 2) + k4;

        const float* xb = xyz + 3 * bb;
        const float x0 = xb[3 * id4.x], y0 = xb[3 * id4.x + 1], z0 = xb[3 * id4.x + 2];
        const float x1 = xb[3 * id4.y], y1 = xb[3 * id4.y + 1], z1 = xb[3 * id4.y + 2];
        const float x2 = xb[3 * id4.z], y2 = xb[3 * id4.z + 1], z2 = xb[3 * id4.z + 2];
        const float x3 = xb[3 * id4.w], y3 = xb[3 * id4.w + 1], z3 = xb[3 * id4.w + 2];
        float4* o = reinterpret_cast<float4*>(out);
        o[((b * 3 + 0) << 14) + o4] = make_float4(x0, x1, x2, x3);
        o[((b * 3 + 1) << 14) + o4] = make_float4(y0, y1, y2, y3);
        o[((b * 3 + 2) << 14) + o4] = make_float4(z0, z1, z2, z3);
    } else {
        const int t  = (blockIdx.x - 256) * 256 + threadIdx.x;  // b(2)|n(12)|k4(2)|cq(2)
        const int cq = t & 3;
        const int k4 = (t >> 2) & 3;
        const int n  = (t >> 4) & (NP - 1);
        const int b  = t >> 16;
        const int bb = b << 12;
        const int4 id4 = reinterpret_cast<const int4*>(g_ids)[((bb + n) << 2) + k4];
        const int o4 = (n << 2) + k4;

        const float4* f0 = reinterpret_cast<const float4*>(feat) + ((bb + id4.x) << 4) + (cq << 2);
        const float4* f1 = reinterpret_cast<const float4*>(feat) + ((bb + id4.y) << 4) + (cq << 2);
        const float4* f2 = reinterpret_cast<const float4*>(feat) + ((bb + id4.z) << 4) + (cq << 2);
        const float4* f3 = reinterpret_cast<const float4*>(feat) + ((bb + id4.w) << 4) + (cq << 2);

        float4* of = reinterpret_cast<float4*>(out) + ((12 + b * 64 + (cq << 4)) << 14) + o4;
        #pragma unroll
        for (int j = 0; j < 4; ++j) {
            const float4 v0 = f0[j], v1 = f1[j], v2 = f2[j], v3 = f3[j];
            of[(4 * j + 0) << 14] = make_float4(v0.x, v1.x, v2.x, v3.x);
            of[(4 * j + 1) << 14] = make_float4(v0.y, v1.y, v2.y, v3.y);
            of[(4 * j + 2) << 14] = make_float4(v0.z, v1.z, v2.z, v3.z);
            of[(4 * j + 3) << 14] = make_float4(v0.w, v1.w, v2.w, v3.w);
        }
    }
}

extern "C" void kernel_launch(void* const* d_in, const int* in_sizes, int n_in,
                              void* d_out, int out_size) {
    const float* xyz  = (const float*)d_in[0];
    const float* feat = (const float*)d_in[1];
    float* out = (float*)d_out;

    build_cs_kernel<<<NB, 1024>>>(xyz);
    scatter_kernel<<<SBLK, 256>>>(xyz);
    query_kernel<<<(NB * NP) / QW, 32 * QW>>>();
    gather_kernel<<<256 + (NB * NP * KOUT) / 256, 256>>>(xyz, feat, out);
}

// round 16
// speedup vs baseline: 3.3527x; 1.0740x over previous
#include <cuda_runtime.h>

// AnnularDilatedKNN: B=4, N=4096, C=64, SAMPLE=16, DILATED_RATE=2 -> NSAMPLE=32, K_out=16
// radius^2 = 256.
//
// R16 = R15 with ONE change: feature-gather read indexing swaps the roles of
// cq and j. Thread cq now reads f[row*256B + j*64B + cq*16B] -> for fixed j
// the 4 cq-threads read contiguous 64B inside ONE 128B line (8 wavefronts per
// load instr instead of 16; rows are 256B aligned). The thread consequently
// owns channels 16j+4cq..+3, so store planes use (j<<4)+(cq<<2)+l -- write
// coalescing unchanged (4 full lines per store instr). Same values to same
// output elements; pure access-order change.
// Build/query/selection byte-identical to the R15 rel_err=0.0 winner.

#define NB     4
#define NP     4096
#define KOUT   16
#define NCY    40
#define NCZ    40
#define NCELL2 (NCY * NCZ)          // 1600
#define CMIN   (-170.0f)
#define INVC   (1.0f / 8.5f)
#define QW     16                   // warps (queries) per query block
#define SBLK   64                   // scatter blocks (256 thr), 16 per batch

__device__ float4 g_cand[NB * NP];           // cell-sorted (x,y,z,sq)
__device__ int    g_sid[NB * NP];            // original index per sorted slot
__device__ int    g_pcell[NB * NP];          // cell per original point
__device__ int    g_cstart[NB * (NCELL2 + 1)];
__device__ int    g_cursor[NB * NCELL2];
__device__ int    g_ids[NB * NP * KOUT];

__device__ __forceinline__ float sq3(float x, float y, float z) {
    // jnp.sum(xyz*xyz, -1): left-to-right, separately rounded products (no fma).
    return __fadd_rn(__fadd_rn(__fmul_rn(x, x), __fmul_rn(y, y)), __fmul_rn(z, z));
}

__device__ __forceinline__ int cell1(float v) {
    int c = (int)floorf(__fmul_rn(__fadd_rn(v, -CMIN), INVC));
    return min(max(c, 0), NCY - 1);
}

// ---- build 1: fused count + scan, one block per batch ----
__global__ __launch_bounds__(1024) void build_cs_kernel(const float* __restrict__ xyz) {
    __shared__ int cnt[NCELL2];                // 6400 B
    __shared__ int wsum[32];
    const int b = blockIdx.x, tid = threadIdx.x;
    const int lane = tid & 31, wid = tid >> 5;

    for (int k = tid; k < NCELL2; k += 1024) cnt[k] = 0;
    __syncthreads();

    #pragma unroll
    for (int j = 0; j < 4; ++j) {
        const int i = (b << 12) + tid + j * 1024;
        const float y = xyz[3 * i + 1];
        const float z = xyz[3 * i + 2];
        const int c = cell1(z) * NCY + cell1(y);
        g_pcell[i] = c;
        atomicAdd(&cnt[c], 1);
    }
    __syncthreads();

    // exclusive scan over 1600 cells: 2 cells/thread (threads 0..799)
    const int c0 = tid * 2;
    int v0 = 0, v1 = 0;
    if (c0 < NCELL2) { v0 = cnt[c0]; v1 = cnt[c0 + 1]; }
    const int s = v0 + v1;
    int incl = s;
    #pragma unroll
    for (int off = 1; off < 32; off <<= 1) {
        const int t = __shfl_up_sync(0xffffffffu, incl, off);
        if (lane >= off) incl += t;
    }
    if (lane == 31) wsum[wid] = incl;
    __syncthreads();
    if (wid == 0) {
        int wv = wsum[lane];
        int wi = wv;
        #pragma unroll
        for (int off = 1; off < 32; off <<= 1) {
            const int t = __shfl_up_sync(0xffffffffu, wi, off);
            if (lane >= off) wi += t;
        }
        wsum[lane] = wi - wv;
    }
    __syncthreads();
    if (c0 < NCELL2) {
        const int excl = (incl - s) + wsum[wid];
        g_cstart[b * (NCELL2 + 1) + c0]     = excl;
        g_cstart[b * (NCELL2 + 1) + c0 + 1] = excl + v0;
        g_cursor[b * NCELL2 + c0]     = excl;
        g_cursor[b * NCELL2 + c0 + 1] = excl + v0;
        if (c0 + 1 == NCELL2 - 1)
            g_cstart[b * (NCELL2 + 1) + NCELL2] = excl + v0 + v1;   // == NP
    }
}

// ---- build 2: scatter via global atomic cursors ----
__global__ __launch_bounds__(256) void scatter_kernel(const float* __restrict__ xyz) {
    const int i = blockIdx.x * 256 + threadIdx.x;
    const int b = i >> 12;
    const int c = g_pcell[i];
    const int pos = atomicAdd(&g_cursor[b * NCELL2 + c], 1);
    const float x = xyz[3 * i + 0];
    const float y = xyz[3 * i + 1];
    const float z = xyz[3 * i + 2];
    const int gi = (b << 12) + pos;
    g_cand[gi] = make_float4(x, y, z, sq3(x, y, z));
    g_sid[gi] = i & (NP - 1);
}

// ---- query: warp per SORTED query; 5 contiguous 2-D runs (+-2 cells) ----
__global__ __launch_bounds__(32 * QW) void query_kernel() {
    __shared__ unsigned bm[QW][128];
    __shared__ int cum[QW][128];

    const int warp = threadIdx.x >> 5, lane = threadIdx.x & 31;
    const int p = blockIdx.x * QW + warp;        // sorted position, 0..16383
    const int b = p >> 12;
    const int bb = b << 12;

    const float4 qc = g_cand[p];
    const int qn = g_sid[p];
    const float xn = qc.x, yn = qc.y, zn = qc.z, sqn = qc.w;

    const int cy = cell1(yn), cz = cell1(zn);
    const int ylo = max(cy - 2, 0), yhi = min(cy + 2, NCY - 1);
    const int zlo = max(cz - 2, 0), zhi = min(cz + 2, NCZ - 1);
    const int* __restrict__ cs = g_cstart + b * (NCELL2 + 1);

    #pragma unroll
    for (int k = 0; k < 4; ++k) bm[warp][lane * 4 + k] = 0u;
    __syncwarp();

    const float4* __restrict__ cand = g_cand + bb;
    const int* __restrict__ sid = g_sid + bb;

    for (int zz = zlo; zz <= zhi; ++zz) {
        const int st = cs[zz * NCY + ylo];
        const int e  = cs[zz * NCY + yhi + 1];
        #pragma unroll 4
        for (int i = st + lane; i < e; i += 32) {
            const float4 c = cand[i];
            // byte-identical verified predicate
            const float dot = fmaf(zn, c.z, fmaf(yn, c.y, __fmul_rn(xn, c.x)));
            const float d2  = __fsub_rn(__fadd_rn(sqn, c.w), __fmul_rn(2.0f, dot));
            if (d2 < 256.0f) {
                const int id = sid[i];
                atomicOr(&bm[warp][id >> 5], 1u << (id & 31));
            }
        }
    }
    __syncwarp();

    // verified selection: popc prefix over 128 words, ranks {0,16..30}
    int c4[4];
    int lsum = 0;
    #pragma unroll
    for (int k = 0; k < 4; ++k) {
        c4[k] = __popc(bm[warp][lane * 4 + k]);
        lsum += c4[k];
    }
    int incl = lsum;
    #pragma unroll
    for (int off = 1; off < 32; off <<= 1) {
        const int t = __shfl_up_sync(0xffffffffu, incl, off);
        if (lane >= off) incl += t;
    }
    const int cnt = __shfl_sync(0xffffffffu, incl, 31);
    int base = incl - lsum;
    #pragma unroll
    for (int k = 0; k < 4; ++k) {
        cum[warp][lane * 4 + k] = base;
        base += c4[k];
    }
    __syncwarp();

    int own = 0;
    const int t = (lane == 0) ? 0 : lane + 15;
    if (lane < 16 && t < cnt) {
        int lo = 0, hi = 127;
        while (lo < hi) {                        // largest word with cum <= t
            const int mid = (lo + hi + 1) >> 1;
            if (cum[warp][mid] <= t) lo = mid; else hi = mid - 1;
        }
        unsigned w = bm[warp][lo];
        int r = t - cum[warp][lo];
        while (r--) w &= (w - 1u);
        own = (lo << 5) + (__ffs(w) - 1);
    }
    const int h0 = __shfl_sync(0xffffffffu, own, 0);  // center (cnt>=1: self-hit)
    if (lane < 16) g_ids[((bb + qn) << 4) + lane] = (t < cnt) ? own : h0;
}

// ---- fused gather: blocks [0,256) = xyz planes, [256,1280) = feature planes ----
__global__ __launch_bounds__(256) void gather_kernel(const float* __restrict__ xyz,
                                                     const float* __restrict__ feat,
                                                     float* __restrict__ out) {
    if (blockIdx.x < 256) {
        const int t  = blockIdx.x * 256 + threadIdx.x;    // b(2)|n(12)|k4(2), 65536 total
        const int k4 = t & 3;
        const int n  = (t >> 2) & (NP - 1);
        const int b  = t >> 14;
        const int bb = b << 12;
        const int4 id4 = reinterpret_cast<const int4*>(g_ids)[t];
        const int o4 = (n << 2) + k4;

        const float* xb = xyz + 3 * bb;
        const float x0 = xb[3 * id4.x], y0 = xb[3 * id4.x + 1], z0 = xb[3 * id4.x + 2];
        const float x1 = xb[3 * id4.y], y1 = xb[3 * id4.y + 1], z1 = xb[3 * id4.y + 2];
        const float x2 = xb[3 * id4.z], y2 = xb[3 * id4.z + 1], z2 = xb[3 * id4.z + 2];
        const float x3 = xb[3 * id4.w], y3 = xb[3 * id4.w + 1], z3 = xb[3 * id4.w + 2];
        float4* o = reinterpret_cast<float4*>(out);
        o[((b * 3 + 0) << 14) + o4] = make_float4(x0, x1, x2, x3);
        o[((b * 3 + 1) << 14) + o4] = make_float4(y0, y1, y2, y3);
        o[((b * 3 + 2) << 14) + o4] = make_float4(z0, z1, z2, z3);
    } else {
        const int t  = (blockIdx.x - 256) * 256 + threadIdx.x;  // b(2)|n(12)|k4(2)|cq(2)
        const int cq = t & 3;
        const int k4 = (t >> 2) & 3;
        const int n  = (t >> 4) & (NP - 1);
        const int b  = t >> 16;
        const int bb = b << 12;
        const int4 id4 = reinterpret_cast<const int4*>(g_ids)[((bb + n) << 2) + k4];
        const int o4 = (n << 2) + k4;

        // row bases (float4 units); thread reads offset j*4 + cq within the row
        const float4* f0 = reinterpret_cast<const float4*>(feat) + ((bb + id4.x) << 4);
        const float4* f1 = reinterpret_cast<const float4*>(feat) + ((bb + id4.y) << 4);
        const float4* f2 = reinterpret_cast<const float4*>(feat) + ((bb + id4.z) << 4);
        const float4* f3 = reinterpret_cast<const float4*>(feat) + ((bb + id4.w) << 4);

        float4* of = reinterpret_cast<float4*>(out) + ((12 + b * 64) << 14) + o4;
        #pragma unroll
        for (int j = 0; j < 4; ++j) {                 // quarter j: contiguous across cq
            const int ro = (j << 2) + cq;             // float4 index within 256B row
            const float4 v0 = f0[ro], v1 = f1[ro], v2 = f2[ro], v3 = f3[ro];
            const int ch = (j << 4) + (cq << 2);      // channels ch..ch+3
            of[(ch + 0) << 14] = make_float4(v0.x, v1.x, v2.x, v3.x);
            of[(ch + 1) << 14] = make_float4(v0.y, v1.y, v2.y, v3.y);
            of[(ch + 2) << 14] = make_float4(v0.z, v1.z, v2.z, v3.z);
            of[(ch + 3) << 14] = make_float4(v0.w, v1.w, v2.w, v3.w);
        }
    }
}

extern "C" void kernel_launch(void* const* d_in, const int* in_sizes, int n_in,
                              void* d_out, int out_size) {
    const float* xyz  = (const float*)d_in[0];
    const float* feat = (const float*)d_in[1];
    float* out = (float*)d_out;

    build_cs_kernel<<<NB, 1024>>>(xyz);
    scatter_kernel<<<SBLK, 256>>>(xyz);
    query_kernel<<<(NB * NP) / QW, 32 * QW>>>();
    gather_kernel<<<256 + (NB * NP * KOUT) / 256, 256>>>(xyz, feat, out);
}